// round 3
// baseline (speedup 1.0000x reference)
#include <cuda_runtime.h>
#include <cuda_bf16.h>
#include <cstddef>

// Problem constants
#define S_TOK 4096      // H*W
#define CDIM  768
#define NH    12
#define HD    64
#define QKV_N (3*CDIM)  // 2304

// ---------------------------------------------------------------------------
// Scratch (device globals; no dynamic allocation allowed)
// ---------------------------------------------------------------------------
__device__ float g_qkv[(size_t)S_TOK * QKV_N];        // 37.7 MB, [token][3*768]
__device__ float g_relh[(size_t)NH * S_TOK * 64];     // 12.6 MB, [h][q][kh]
__device__ float g_relw[(size_t)NH * S_TOK * 64];     // 12.6 MB, [h][q][kw]
__device__ float g_attno[(size_t)S_TOK * CDIM];       // 12.6 MB, [token][h*64+d]

// ---------------------------------------------------------------------------
// Generic tiled GEMM + bias: C[M,N] = A[M,K] @ B[K,N] + bias[N]
// BM=BN=128, BK=16, 256 threads, 8x8 per thread. M%128==0, N%128==0, K%16==0.
// ---------------------------------------------------------------------------
__global__ __launch_bounds__(256) void gemm_bias_kernel(
    const float* __restrict__ A, const float* __restrict__ B,
    const float* __restrict__ bias, float* __restrict__ C,
    int M, int N, int K)
{
    __shared__ __align__(16) float As[16][132];   // transposed A tile, padded
    __shared__ __align__(16) float Bs[16][128];

    const int tid = threadIdx.x;
    const int tx = tid & 15;
    const int ty = tid >> 4;
    const int m0 = blockIdx.y * 128;
    const int n0 = blockIdx.x * 128;

    float acc[8][8];
#pragma unroll
    for (int i = 0; i < 8; i++)
#pragma unroll
        for (int j = 0; j < 8; j++) acc[i][j] = 0.f;

    const int arow = tid >> 2;          // 0..63 (+64 second pass)
    const int acol = (tid & 3) << 2;    // 0,4,8,12
    const int brow = tid >> 5;          // 0..7 (+8 second pass)
    const int bcol = (tid & 31) << 2;   // 0..124

    for (int k0 = 0; k0 < K; k0 += 16) {
#pragma unroll
        for (int p = 0; p < 2; p++) {
            int r = arow + p * 64;
            float4 av = *(const float4*)(A + (size_t)(m0 + r) * K + k0 + acol);
            As[acol + 0][r] = av.x;
            As[acol + 1][r] = av.y;
            As[acol + 2][r] = av.z;
            As[acol + 3][r] = av.w;
        }
#pragma unroll
        for (int p = 0; p < 2; p++) {
            int r = brow + p * 8;
            *(float4*)&Bs[r][bcol] =
                *(const float4*)(B + (size_t)(k0 + r) * N + n0 + bcol);
        }
        __syncthreads();

#pragma unroll
        for (int kk = 0; kk < 16; kk++) {
            float a[8], b[8];
            *(float4*)&a[0] = *(float4*)&As[kk][ty * 8];
            *(float4*)&a[4] = *(float4*)&As[kk][ty * 8 + 4];
            *(float4*)&b[0] = *(float4*)&Bs[kk][tx * 8];
            *(float4*)&b[4] = *(float4*)&Bs[kk][tx * 8 + 4];
#pragma unroll
            for (int i = 0; i < 8; i++)
#pragma unroll
                for (int j = 0; j < 8; j++)
                    acc[i][j] += a[i] * b[j];
        }
        __syncthreads();
    }

#pragma unroll
    for (int i = 0; i < 8; i++) {
        int m = m0 + ty * 8 + i;
#pragma unroll
        for (int j = 0; j < 8; j += 4) {
            int n = n0 + tx * 8 + j;
            float4 bv = *(const float4*)(bias + n);
            float4 cv;
            cv.x = acc[i][j + 0] + bv.x;
            cv.y = acc[i][j + 1] + bv.y;
            cv.z = acc[i][j + 2] + bv.z;
            cv.w = acc[i][j + 3] + bv.w;
            *(float4*)(C + (size_t)m * N + n) = cv;
        }
    }
}

// ---------------------------------------------------------------------------
// Relative-position tables.
// mode 0 (rel_h): blockIdx.x = qh.  out[qw][kh] = sum_c q[qh,qw,c]*rph[qh-kh+63][c]
//                 stored at g_tbl[h][qh*64+qw][kh]
// mode 1 (rel_w): blockIdx.x = qw.  out[qh][kw] = sum_c q[qh,qw,c]*rpw[qw-kw+63][c]
//                 stored at g_tbl[h][qh*64+qw][kw]
// q is the UNSCALED q section of g_qkv.
// ---------------------------------------------------------------------------
__global__ __launch_bounds__(256) void relpos_kernel(
    const float* __restrict__ relpos,   // (127, 64)
    float* __restrict__ tbl,            // (NH, 4096, 64)
    int mode)
{
    __shared__ __align__(16) float Qt[64][68];
    __shared__ __align__(16) float Rt[64][68];

    const int tid = threadIdx.x;
    const int h = blockIdx.y;
    const int fixed = blockIdx.x;   // qh (mode 0) or qw (mode 1)

#pragma unroll
    for (int p = 0; p < 4; p++) {
        int f4 = tid + 256 * p;
        int r = f4 >> 4;
        int c4 = (f4 & 15) << 2;
        int token = (mode == 0) ? (fixed * 64 + r) : (r * 64 + fixed);
        *(float4*)&Qt[r][c4] =
            *(const float4*)(g_qkv + (size_t)token * QKV_N + h * 64 + c4);
        int ridx = fixed - r + 63;          // r plays role of k index for Rt
        *(float4*)&Rt[r][c4] = *(const float4*)(relpos + ridx * 64 + c4);
    }
    __syncthreads();

    const int tx = tid & 15;
    const int ty = tid >> 4;
    float s[4][4];
#pragma unroll
    for (int i = 0; i < 4; i++)
#pragma unroll
        for (int j = 0; j < 4; j++) s[i][j] = 0.f;

#pragma unroll
    for (int c4 = 0; c4 < 16; c4++) {
        float qr[4][4], kr[4][4];
#pragma unroll
        for (int i = 0; i < 4; i++)
            *(float4*)&qr[i][0] = *(float4*)&Qt[ty + 16 * i][c4 * 4];
#pragma unroll
        for (int j = 0; j < 4; j++)
            *(float4*)&kr[j][0] = *(float4*)&Rt[tx + 16 * j][c4 * 4];
#pragma unroll
        for (int e = 0; e < 4; e++)
#pragma unroll
            for (int i = 0; i < 4; i++)
#pragma unroll
                for (int j = 0; j < 4; j++)
                    s[i][j] += qr[i][e] * kr[j][e];
    }

#pragma unroll
    for (int i = 0; i < 4; i++) {
        int a = ty + 16 * i;
        int token = (mode == 0) ? (fixed * 64 + a) : (a * 64 + fixed);
#pragma unroll
        for (int j = 0; j < 4; j++) {
            int b = tx + 16 * j;
            tbl[((size_t)h * S_TOK + token) * 64 + b] = s[i][j];
        }
    }
}

// ---------------------------------------------------------------------------
// Flash attention with decomposed rel-pos bias.
// Block = (q-tile of 64 queries) x head.  256 threads, 4x4 register tiles
// with interleaved mapping (qi = ty+16i, kj/dj = tx+16j).
// Key tiles of 64 keys == one kh row, so bias = RH[q] (scalar/tile) + RW[q][kw].
// ---------------------------------------------------------------------------
#define FLASH_SMEM_FLOATS (5 * 64 * 68 + 64)
#define FLASH_SMEM_BYTES  (FLASH_SMEM_FLOATS * 4)

__global__ __launch_bounds__(256) void flash_kernel(float* __restrict__ out)
{
    extern __shared__ __align__(16) float sm[];
    float* Qs = sm;                  // [64][68], pre-scaled q
    float* Ks = sm + 1 * 64 * 68;    // [64][68]
    float* Vs = sm + 2 * 64 * 68;    // [64][68]
    float* Ps = sm + 3 * 64 * 68;    // [64][68]
    float* RW = sm + 4 * 64 * 68;    // [64][68] rel_w rows for this q-tile
    float* RH = sm + 5 * 64 * 68;    // [64] per-tile rel_h scalars

    const int tid = threadIdx.x;
    const int tx = tid & 15;
    const int ty = tid >> 4;
    const int h = blockIdx.y;
    const int q0 = blockIdx.x * 64;
    const float scale = 0.125f;      // 64^-0.5

    // Load Q tile (scaled) and rel_w rows once.
#pragma unroll
    for (int p = 0; p < 4; p++) {
        int f4 = tid + 256 * p;
        int r = f4 >> 4;
        int c4 = (f4 & 15) << 2;
        float4 qv = *(const float4*)(g_qkv + (size_t)(q0 + r) * QKV_N + h * 64 + c4);
        qv.x *= scale; qv.y *= scale; qv.z *= scale; qv.w *= scale;
        *(float4*)&Qs[r * 68 + c4] = qv;
        *(float4*)&RW[r * 68 + c4] =
            *(const float4*)(g_relw + ((size_t)h * S_TOK + q0 + r) * 64 + c4);
    }

    float m_i[4], l_i[4], O[4][4];
#pragma unroll
    for (int i = 0; i < 4; i++) {
        m_i[i] = -1e30f;
        l_i[i] = 0.f;
#pragma unroll
        for (int j = 0; j < 4; j++) O[i][j] = 0.f;
    }

    for (int kt = 0; kt < 64; kt++) {
        __syncthreads();   // previous PV done before overwriting Ks/Vs (also covers Q load on kt=0)
#pragma unroll
        for (int p = 0; p < 4; p++) {
            int f4 = tid + 256 * p;
            int r = f4 >> 4;
            int c4 = (f4 & 15) << 2;
            const float* base = g_qkv + (size_t)(kt * 64 + r) * QKV_N + h * 64 + c4;
            *(float4*)&Ks[r * 68 + c4] = *(const float4*)(base + CDIM);
            *(float4*)&Vs[r * 68 + c4] = *(const float4*)(base + 2 * CDIM);
        }
        if (tid < 64)
            RH[tid] = g_relh[((size_t)h * S_TOK + q0 + tid) * 64 + kt];
        __syncthreads();

        // ---- S = scale*Q @ K^T ----
        float s[4][4];
#pragma unroll
        for (int i = 0; i < 4; i++)
#pragma unroll
            for (int j = 0; j < 4; j++) s[i][j] = 0.f;

#pragma unroll
        for (int c4 = 0; c4 < 16; c4++) {
            float qr[4][4], kr[4][4];
#pragma unroll
            for (int i = 0; i < 4; i++)
                *(float4*)&qr[i][0] = *(float4*)&Qs[(ty + 16 * i) * 68 + 4 * c4];
#pragma unroll
            for (int j = 0; j < 4; j++)
                *(float4*)&kr[j][0] = *(float4*)&Ks[(tx + 16 * j) * 68 + 4 * c4];
#pragma unroll
            for (int e = 0; e < 4; e++)
#pragma unroll
                for (int i = 0; i < 4; i++)
#pragma unroll
                    for (int j = 0; j < 4; j++)
                        s[i][j] += qr[i][e] * kr[j][e];
        }

        // ---- bias + online softmax ----
#pragma unroll
        for (int i = 0; i < 4; i++) {
            int qi = ty + 16 * i;
            float rh = RH[qi];
            float rowmax = -1e30f;
#pragma unroll
            for (int j = 0; j < 4; j++) {
                s[i][j] += rh + RW[qi * 68 + tx + 16 * j];
                rowmax = fmaxf(rowmax, s[i][j]);
            }
#pragma unroll
            for (int off = 8; off >= 1; off >>= 1)
                rowmax = fmaxf(rowmax, __shfl_xor_sync(0xffffffffu, rowmax, off));
            float mnew = fmaxf(m_i[i], rowmax);
            float alpha = __expf(m_i[i] - mnew);
            float rs = 0.f;
#pragma unroll
            for (int j = 0; j < 4; j++) {
                s[i][j] = __expf(s[i][j] - mnew);
                rs += s[i][j];
            }
#pragma unroll
            for (int off = 8; off >= 1; off >>= 1)
                rs += __shfl_xor_sync(0xffffffffu, rs, off);
            l_i[i] = l_i[i] * alpha + rs;
            m_i[i] = mnew;
#pragma unroll
            for (int j = 0; j < 4; j++) O[i][j] *= alpha;
        }

        // ---- write P (region unused by other phases; no pre-sync needed) ----
#pragma unroll
        for (int i = 0; i < 4; i++)
#pragma unroll
            for (int j = 0; j < 4; j++)
                Ps[(ty + 16 * i) * 68 + tx + 16 * j] = s[i][j];
        __syncthreads();

        // ---- O += P @ V ----
#pragma unroll
        for (int k4 = 0; k4 < 16; k4++) {
            float pr[4][4];
#pragma unroll
            for (int i = 0; i < 4; i++)
                *(float4*)&pr[i][0] = *(float4*)&Ps[(ty + 16 * i) * 68 + 4 * k4];
#pragma unroll
            for (int u = 0; u < 4; u++) {
                float vv[4];
#pragma unroll
                for (int j = 0; j < 4; j++)
                    vv[j] = Vs[(4 * k4 + u) * 68 + tx + 16 * j];
#pragma unroll
                for (int i = 0; i < 4; i++)
#pragma unroll
                    for (int j = 0; j < 4; j++)
                        O[i][j] += pr[i][u] * vv[j];
            }
        }
    }

    // ---- epilogue: normalize and store (channel = h*64 + d) ----
#pragma unroll
    for (int i = 0; i < 4; i++) {
        float inv = 1.f / l_i[i];
        int q = q0 + ty + 16 * i;
#pragma unroll
        for (int j = 0; j < 4; j++)
            out[(size_t)q * CDIM + h * 64 + tx + 16 * j] = O[i][j] * inv;
    }
}

// ---------------------------------------------------------------------------
// Launch
// ---------------------------------------------------------------------------
extern "C" void kernel_launch(void* const* d_in, const int* in_sizes, int n_in,
                              void* d_out, int out_size)
{
    const float* x      = (const float*)d_in[0];   // (1,64,64,768) -> [4096][768]
    const float* qkv_w  = (const float*)d_in[1];   // [768][2304]
    const float* qkv_b  = (const float*)d_in[2];   // [2304]
    const float* rph    = (const float*)d_in[3];   // [127][64]
    const float* rpw    = (const float*)d_in[4];   // [127][64]
    const float* proj_w = (const float*)d_in[5];   // [768][768]
    const float* proj_b = (const float*)d_in[6];   // [768]
    float* out = (float*)d_out;                    // [4096][768]

    float *qkv, *relh, *relw, *attno;
    cudaGetSymbolAddress((void**)&qkv,   g_qkv);
    cudaGetSymbolAddress((void**)&relh,  g_relh);
    cudaGetSymbolAddress((void**)&relw,  g_relw);
    cudaGetSymbolAddress((void**)&attno, g_attno);

    cudaFuncSetAttribute(flash_kernel,
                         cudaFuncAttributeMaxDynamicSharedMemorySize,
                         FLASH_SMEM_BYTES);

    // 1. qkv = x @ qkv_w + qkv_b
    {
        dim3 grid(QKV_N / 128, S_TOK / 128);
        gemm_bias_kernel<<<grid, 256>>>(x, qkv_w, qkv_b, qkv,
                                        S_TOK, QKV_N, CDIM);
    }
    // 2. rel-pos tables (from unscaled q)
    {
        dim3 grid(64, NH);
        relpos_kernel<<<grid, 256>>>(rph, relh, 0);
        relpos_kernel<<<grid, 256>>>(rpw, relw, 1);
    }
    // 3. flash attention with bias
    {
        dim3 grid(S_TOK / 64, NH);
        flash_kernel<<<grid, 256, FLASH_SMEM_BYTES>>>(attno);
    }
    // 4. out = attno @ proj_w + proj_b
    {
        dim3 grid(CDIM / 128, S_TOK / 128);
        gemm_bias_kernel<<<grid, 256>>>(attno, proj_w, proj_b, out,
                                        S_TOK, CDIM, CDIM);
    }
}

// round 5
// speedup vs baseline: 1.5546x; 1.5546x over previous
#include <cuda_runtime.h>
#include <cuda_bf16.h>
#include <cstdint>
#include <cstddef>

// Problem constants
#define S_TOK 4096      // H*W
#define CDIM  768
#define NH    12
#define QKV_N (3*CDIM)  // 2304

// ---------------------------------------------------------------------------
// Scratch (device globals; no dynamic allocation allowed)
// ---------------------------------------------------------------------------
__device__ float g_qkv[(size_t)S_TOK * QKV_N];        // [token][3*768]
__device__ float g_relh[(size_t)NH * S_TOK * 64];     // [h][q][kh]
__device__ float g_relw[(size_t)NH * S_TOK * 64];     // [h][q][kw]
__device__ float g_attno[(size_t)S_TOK * CDIM];       // [token][h*64+d]

// ---------------------------------------------------------------------------
// tf32 mma.sync helpers (sm_80-level PTX; works on compute_103 base target)
// ---------------------------------------------------------------------------
__device__ __forceinline__ uint32_t f2tf32(float f) {
    uint32_t u;
    asm("cvt.rna.tf32.f32 %0, %1;" : "=r"(u) : "f"(f));
    return u;
}

__device__ __forceinline__ void mma_tf32(float* c, const uint4& a, const uint2& b) {
    asm volatile(
        "mma.sync.aligned.m16n8k8.row.col.f32.tf32.tf32.f32 "
        "{%0,%1,%2,%3}, {%4,%5,%6,%7}, {%8,%9}, {%0,%1,%2,%3};"
        : "+f"(c[0]), "+f"(c[1]), "+f"(c[2]), "+f"(c[3])
        : "r"(a.x), "r"(a.y), "r"(a.z), "r"(a.w), "r"(b.x), "r"(b.y));
}

// ---------------------------------------------------------------------------
// Generic tiled GEMM + bias (unchanged SIMT fp32; exact)
// ---------------------------------------------------------------------------
__global__ __launch_bounds__(256) void gemm_bias_kernel(
    const float* __restrict__ A, const float* __restrict__ B,
    const float* __restrict__ bias, float* __restrict__ C,
    int M, int N, int K)
{
    __shared__ __align__(16) float As[16][132];
    __shared__ __align__(16) float Bs[16][128];

    const int tid = threadIdx.x;
    const int tx = tid & 15;
    const int ty = tid >> 4;
    const int m0 = blockIdx.y * 128;
    const int n0 = blockIdx.x * 128;

    float acc[8][8];
#pragma unroll
    for (int i = 0; i < 8; i++)
#pragma unroll
        for (int j = 0; j < 8; j++) acc[i][j] = 0.f;

    const int arow = tid >> 2;
    const int acol = (tid & 3) << 2;
    const int brow = tid >> 5;
    const int bcol = (tid & 31) << 2;

    for (int k0 = 0; k0 < K; k0 += 16) {
#pragma unroll
        for (int p = 0; p < 2; p++) {
            int r = arow + p * 64;
            float4 av = *(const float4*)(A + (size_t)(m0 + r) * K + k0 + acol);
            As[acol + 0][r] = av.x;
            As[acol + 1][r] = av.y;
            As[acol + 2][r] = av.z;
            As[acol + 3][r] = av.w;
        }
#pragma unroll
        for (int p = 0; p < 2; p++) {
            int r = brow + p * 8;
            *(float4*)&Bs[r][bcol] =
                *(const float4*)(B + (size_t)(k0 + r) * N + n0 + bcol);
        }
        __syncthreads();

#pragma unroll
        for (int kk = 0; kk < 16; kk++) {
            float a[8], b[8];
            *(float4*)&a[0] = *(float4*)&As[kk][ty * 8];
            *(float4*)&a[4] = *(float4*)&As[kk][ty * 8 + 4];
            *(float4*)&b[0] = *(float4*)&Bs[kk][tx * 8];
            *(float4*)&b[4] = *(float4*)&Bs[kk][tx * 8 + 4];
#pragma unroll
            for (int i = 0; i < 8; i++)
#pragma unroll
                for (int j = 0; j < 8; j++)
                    acc[i][j] += a[i] * b[j];
        }
        __syncthreads();
    }

#pragma unroll
    for (int i = 0; i < 8; i++) {
        int m = m0 + ty * 8 + i;
#pragma unroll
        for (int j = 0; j < 8; j += 4) {
            int n = n0 + tx * 8 + j;
            float4 bv = *(const float4*)(bias + n);
            float4 cv;
            cv.x = acc[i][j + 0] + bv.x;
            cv.y = acc[i][j + 1] + bv.y;
            cv.z = acc[i][j + 2] + bv.z;
            cv.w = acc[i][j + 3] + bv.w;
            *(float4*)(C + (size_t)m * N + n) = cv;
        }
    }
}

// ---------------------------------------------------------------------------
// Relative-position tables (unchanged)
// ---------------------------------------------------------------------------
__global__ __launch_bounds__(256) void relpos_kernel(
    const float* __restrict__ relpos, float* __restrict__ tbl, int mode)
{
    __shared__ __align__(16) float Qt[64][68];
    __shared__ __align__(16) float Rt[64][68];

    const int tid = threadIdx.x;
    const int h = blockIdx.y;
    const int fixed = blockIdx.x;

#pragma unroll
    for (int p = 0; p < 4; p++) {
        int f4 = tid + 256 * p;
        int r = f4 >> 4;
        int c4 = (f4 & 15) << 2;
        int token = (mode == 0) ? (fixed * 64 + r) : (r * 64 + fixed);
        *(float4*)&Qt[r][c4] =
            *(const float4*)(g_qkv + (size_t)token * QKV_N + h * 64 + c4);
        int ridx = fixed - r + 63;
        *(float4*)&Rt[r][c4] = *(const float4*)(relpos + ridx * 64 + c4);
    }
    __syncthreads();

    const int tx = tid & 15;
    const int ty = tid >> 4;
    float s[4][4];
#pragma unroll
    for (int i = 0; i < 4; i++)
#pragma unroll
        for (int j = 0; j < 4; j++) s[i][j] = 0.f;

#pragma unroll
    for (int c4 = 0; c4 < 16; c4++) {
        float qr[4][4], kr[4][4];
#pragma unroll
        for (int i = 0; i < 4; i++)
            *(float4*)&qr[i][0] = *(float4*)&Qt[ty + 16 * i][c4 * 4];
#pragma unroll
        for (int j = 0; j < 4; j++)
            *(float4*)&kr[j][0] = *(float4*)&Rt[tx + 16 * j][c4 * 4];
#pragma unroll
        for (int e = 0; e < 4; e++)
#pragma unroll
            for (int i = 0; i < 4; i++)
#pragma unroll
                for (int j = 0; j < 4; j++)
                    s[i][j] += qr[i][e] * kr[j][e];
    }

#pragma unroll
    for (int i = 0; i < 4; i++) {
        int a = ty + 16 * i;
        int token = (mode == 0) ? (fixed * 64 + a) : (a * 64 + fixed);
#pragma unroll
        for (int j = 0; j < 4; j++) {
            int b = tx + 16 * j;
            tbl[((size_t)h * S_TOK + token) * 64 + b] = s[i][j];
        }
    }
}

// ---------------------------------------------------------------------------
// Flash attention with tf32 mma.sync (m16n8k8).
// CTA: 128 queries x head. 4 warps; warp w owns q rows [w*32, w*32+32)
// as two 16-row m-blocks. Key tiles of 64 keys (== one kh row).
// All operands staged in SMEM in exact fragment order:
//   A-frags (Q, P):  [w][mb][ks][lane][4] -> one LDS.128
//   B-frags (K, V):  [ks][nt][lane][2]    -> one LDS.64
//   RWf (bias):      [w][mb][nt][lane][4] -> matches C layout
// ---------------------------------------------------------------------------
#define QF_OFF   0            // 8192 f32 = 32KB
#define RWF_OFF  32768        // 8192 f32 = 32KB
#define PF_OFF   65536        // 8192 f32 = 32KB
#define RHS_OFF  98304        // 128*68 f32 = 34816B
#define KF_OFF   133120       // 4096 f32 = 16KB
#define VF_OFF   149504       // 4096 f32 = 16KB
#define FLASH_SMEM 165888

__global__ __launch_bounds__(128, 1) void flash_mma_kernel(float* __restrict__ out)
{
    extern __shared__ __align__(16) char smc[];
    uint32_t* sQf  = (uint32_t*)(smc + QF_OFF);
    float*    sRWf = (float*)   (smc + RWF_OFF);
    uint32_t* sPf  = (uint32_t*)(smc + PF_OFF);
    float*    sRHs = (float*)   (smc + RHS_OFF);
    uint32_t* sKf  = (uint32_t*)(smc + KF_OFF);
    uint32_t* sVf  = (uint32_t*)(smc + VF_OFF);

    const int tid  = threadIdx.x;
    const int w    = tid >> 5;
    const int lane = tid & 31;
    const int h    = blockIdx.y;
    const int q0   = blockIdx.x * 128;

    // ---- prologue: Q (scaled, tf32), rel_w (frag order), rel_h rows ----
    {
        const int r   = tid;               // q row within tile
        const int wb  = r >> 5;
        const int mb  = (r >> 4) & 1;
        const int rho = r & 15;
        const int hh  = rho >> 3;
        const int lb  = (rho & 7) * 4;
        const float* qrow  = g_qkv + (size_t)(q0 + r) * QKV_N + h * 64;
        const float* rwrow = g_relw + ((size_t)h * S_TOK + q0 + r) * 64;
        const float* rhrow = g_relh + ((size_t)h * S_TOK + q0 + r) * 64;
#pragma unroll
        for (int c4 = 0; c4 < 64; c4 += 4) {
            float4 qv = *(const float4*)(qrow + c4);
            float qe[4] = {qv.x * 0.125f, qv.y * 0.125f, qv.z * 0.125f, qv.w * 0.125f};
            float4 rwv = *(const float4*)(rwrow + c4);
            float re[4] = {rwv.x, rwv.y, rwv.z, rwv.w};
#pragma unroll
            for (int i = 0; i < 4; i++) {
                int c  = c4 + i;
                // Q -> A-frag order
                int fi = hh + 2 * ((c & 7) >> 2);
                int ln = lb + (c & 3);
                int ks = c >> 3;
                sQf[(((wb * 2 + mb) * 8 + ks) * 32 + ln) * 4 + fi] = f2tf32(qe[i]);
                // rel_w -> C-frag order
                int fj = 2 * hh + (c & 1);
                int lj = lb + ((c & 7) >> 1);
                int nt = c >> 3;
                sRWf[(((wb * 2 + mb) * 8 + nt) * 32 + lj) * 4 + fj] = re[i];
            }
            *(float4*)(sRHs + r * 68 + c4) = *(const float4*)(rhrow + c4);
        }
    }
    __syncthreads();

    float Sa[2][8][4];
    float Oa[2][8][4];
    float m_[2][2], l_[2][2];
#pragma unroll
    for (int mb = 0; mb < 2; mb++) {
        m_[mb][0] = -1e30f; m_[mb][1] = -1e30f;
        l_[mb][0] = 0.f;    l_[mb][1] = 0.f;
#pragma unroll
        for (int nt = 0; nt < 8; nt++)
#pragma unroll
            for (int j = 0; j < 4; j++) Oa[mb][nt][j] = 0.f;
    }

    // precomputed P-scatter addressing for this lane
    const int g0 = 2 * (lane & 3);
    const int g1 = g0 + 1;
    const int lam0 = ((lane >> 2) << 2) + (g0 & 3);
    const int lam1 = ((lane >> 2) << 2) + (g1 & 3);
    const int fb0  = (g0 >> 2) << 1;
    const int fb1  = (g1 >> 2) << 1;

    const int lr = tid >> 1;            // loader row (key) 0..63
    const int cb = (tid & 1) * 32;      // loader col base

    for (int kt = 0; kt < 64; kt++) {
        // ---- gmem loads for K,V tile (to regs) ----
        const float* kbase = g_qkv + (size_t)(kt * 64 + lr) * QKV_N + h * 64 + CDIM + cb;
        const float* vbase = kbase + CDIM;
        float4 ka[8], va[8];
#pragma unroll
        for (int g = 0; g < 4; g++) {
            ka[2 * g]     = *(const float4*)(kbase + g * 8);
            ka[2 * g + 1] = *(const float4*)(kbase + g * 8 + 4);
            va[2 * g]     = *(const float4*)(vbase + g * 8);
            va[2 * g + 1] = *(const float4*)(vbase + g * 8 + 4);
        }
        __syncthreads();   // prior tile's Kf/Vf consumers done

        // ---- STS K (B-frag pairs) + V (scatter) ----
#pragma unroll
        for (int g = 0; g < 4; g++) {
            int ks = (cb >> 3) + g;
            int nt = lr >> 3;
            int l0 = (lr & 7) * 4;
            uint32_t* dst = sKf + ((ks * 8 + nt) * 32 + l0) * 2;
            uint4 s1 = {f2tf32(ka[2*g].x), f2tf32(ka[2*g+1].x),
                        f2tf32(ka[2*g].y), f2tf32(ka[2*g+1].y)};
            uint4 s2 = {f2tf32(ka[2*g].z), f2tf32(ka[2*g+1].z),
                        f2tf32(ka[2*g].w), f2tf32(ka[2*g+1].w)};
            *(uint4*)dst       = s1;
            *(uint4*)(dst + 4) = s2;

            int ksv  = lr >> 3;
            int ntv  = (cb >> 3) + g;
            int slot = (lr & 7) >> 2;
            int rl   = lr & 3;
            uint32_t* vdst = sVf + ((ksv * 8 + ntv) * 32) * 2;
            float ve[8] = {va[2*g].x, va[2*g].y, va[2*g].z, va[2*g].w,
                           va[2*g+1].x, va[2*g+1].y, va[2*g+1].z, va[2*g+1].w};
#pragma unroll
            for (int e = 0; e < 8; e++)
                vdst[(e * 4 + rl) * 2 + slot] = f2tf32(ve[e]);
        }
        __syncthreads();

        // ---- S = Q @ K^T ----
#pragma unroll
        for (int mb = 0; mb < 2; mb++)
#pragma unroll
            for (int nt = 0; nt < 8; nt++)
#pragma unroll
                for (int j = 0; j < 4; j++) Sa[mb][nt][j] = 0.f;

#pragma unroll
        for (int ks = 0; ks < 8; ks++) {
            uint4 a0 = *(uint4*)(sQf + (((w * 2 + 0) * 8 + ks) * 32 + lane) * 4);
            uint4 a1 = *(uint4*)(sQf + (((w * 2 + 1) * 8 + ks) * 32 + lane) * 4);
#pragma unroll
            for (int nt = 0; nt < 8; nt++) {
                uint2 b = *(uint2*)(sKf + ((ks * 8 + nt) * 32 + lane) * 2);
                mma_tf32(Sa[0][nt], a0, b);
                mma_tf32(Sa[1][nt], a1, b);
            }
        }

        // ---- bias + online softmax + P staging ----
        float alpha[2][2];
#pragma unroll
        for (int mb = 0; mb < 2; mb++) {
            int rbase = w * 32 + mb * 16 + (lane >> 2);
            float rhl = sRHs[rbase * 68 + kt];
            float rhh = sRHs[(rbase + 8) * 68 + kt];
            float mlo = -1e30f, mhi = -1e30f;
#pragma unroll
            for (int nt = 0; nt < 8; nt++) {
                float4 rw = *(float4*)(sRWf + (((w * 2 + mb) * 8 + nt) * 32 + lane) * 4);
                Sa[mb][nt][0] += rhl + rw.x;
                Sa[mb][nt][1] += rhl + rw.y;
                Sa[mb][nt][2] += rhh + rw.z;
                Sa[mb][nt][3] += rhh + rw.w;
                mlo = fmaxf(mlo, fmaxf(Sa[mb][nt][0], Sa[mb][nt][1]));
                mhi = fmaxf(mhi, fmaxf(Sa[mb][nt][2], Sa[mb][nt][3]));
            }
            mlo = fmaxf(mlo, __shfl_xor_sync(0xffffffffu, mlo, 1));
            mlo = fmaxf(mlo, __shfl_xor_sync(0xffffffffu, mlo, 2));
            mhi = fmaxf(mhi, __shfl_xor_sync(0xffffffffu, mhi, 1));
            mhi = fmaxf(mhi, __shfl_xor_sync(0xffffffffu, mhi, 2));
            float mnl = fmaxf(m_[mb][0], mlo);
            float mnh = fmaxf(m_[mb][1], mhi);
            alpha[mb][0] = __expf(m_[mb][0] - mnl);
            alpha[mb][1] = __expf(m_[mb][1] - mnh);
            m_[mb][0] = mnl;
            m_[mb][1] = mnh;
            float rsl = 0.f, rsh = 0.f;
#pragma unroll
            for (int nt = 0; nt < 8; nt++) {
                float p0 = __expf(Sa[mb][nt][0] - mnl);
                float p1 = __expf(Sa[mb][nt][1] - mnl);
                float p2 = __expf(Sa[mb][nt][2] - mnh);
                float p3 = __expf(Sa[mb][nt][3] - mnh);
                rsl += p0 + p1;
                rsh += p2 + p3;
                uint32_t base = ((w * 2 + mb) * 8 + nt) * 32;
                sPf[(base + lam0) * 4 + fb0 + 0] = f2tf32(p0);
                sPf[(base + lam1) * 4 + fb1 + 0] = f2tf32(p1);
                sPf[(base + lam0) * 4 + fb0 + 1] = f2tf32(p2);
                sPf[(base + lam1) * 4 + fb1 + 1] = f2tf32(p3);
            }
            rsl += __shfl_xor_sync(0xffffffffu, rsl, 1);
            rsl += __shfl_xor_sync(0xffffffffu, rsl, 2);
            rsh += __shfl_xor_sync(0xffffffffu, rsh, 1);
            rsh += __shfl_xor_sync(0xffffffffu, rsh, 2);
            l_[mb][0] = l_[mb][0] * alpha[mb][0] + rsl;
            l_[mb][1] = l_[mb][1] * alpha[mb][1] + rsh;
        }

        // ---- pre-scale O by alpha, then O += P @ V ----
#pragma unroll
        for (int mb = 0; mb < 2; mb++)
#pragma unroll
            for (int nt = 0; nt < 8; nt++) {
                Oa[mb][nt][0] *= alpha[mb][0];
                Oa[mb][nt][1] *= alpha[mb][0];
                Oa[mb][nt][2] *= alpha[mb][1];
                Oa[mb][nt][3] *= alpha[mb][1];
            }
        __syncwarp();

#pragma unroll
        for (int ks = 0; ks < 8; ks++) {
            uint4 p0 = *(uint4*)(sPf + (((w * 2 + 0) * 8 + ks) * 32 + lane) * 4);
            uint4 p1 = *(uint4*)(sPf + (((w * 2 + 1) * 8 + ks) * 32 + lane) * 4);
#pragma unroll
            for (int nt = 0; nt < 8; nt++) {
                uint2 b = *(uint2*)(sVf + ((ks * 8 + nt) * 32 + lane) * 2);
                mma_tf32(Oa[0][nt], p0, b);
                mma_tf32(Oa[1][nt], p1, b);
            }
        }
    }

    // ---- epilogue: normalize, store ----
#pragma unroll
    for (int mb = 0; mb < 2; mb++) {
        float invl = 1.f / l_[mb][0];
        float invh = 1.f / l_[mb][1];
        int qlo = q0 + w * 32 + mb * 16 + (lane >> 2);
#pragma unroll
        for (int nt = 0; nt < 8; nt++) {
            int col = h * 64 + nt * 8 + 2 * (lane & 3);
            float2 v0 = {Oa[mb][nt][0] * invl, Oa[mb][nt][1] * invl};
            float2 v1 = {Oa[mb][nt][2] * invh, Oa[mb][nt][3] * invh};
            *(float2*)(out + (size_t)qlo * CDIM + col)       = v0;
            *(float2*)(out + (size_t)(qlo + 8) * CDIM + col) = v1;
        }
    }
}

// ---------------------------------------------------------------------------
// Launch
// ---------------------------------------------------------------------------
extern "C" void kernel_launch(void* const* d_in, const int* in_sizes, int n_in,
                              void* d_out, int out_size)
{
    const float* x      = (const float*)d_in[0];
    const float* qkv_w  = (const float*)d_in[1];
    const float* qkv_b  = (const float*)d_in[2];
    const float* rph    = (const float*)d_in[3];
    const float* rpw    = (const float*)d_in[4];
    const float* proj_w = (const float*)d_in[5];
    const float* proj_b = (const float*)d_in[6];
    float* out = (float*)d_out;

    float *qkv, *relh, *relw, *attno;
    cudaGetSymbolAddress((void**)&qkv,   g_qkv);
    cudaGetSymbolAddress((void**)&relh,  g_relh);
    cudaGetSymbolAddress((void**)&relw,  g_relw);
    cudaGetSymbolAddress((void**)&attno, g_attno);

    cudaFuncSetAttribute(flash_mma_kernel,
                         cudaFuncAttributeMaxDynamicSharedMemorySize,
                         FLASH_SMEM);

    // 1. qkv = x @ qkv_w + qkv_b
    {
        dim3 grid(QKV_N / 128, S_TOK / 128);
        gemm_bias_kernel<<<grid, 256>>>(x, qkv_w, qkv_b, qkv,
                                        S_TOK, QKV_N, CDIM);
    }
    // 2. rel-pos tables (from unscaled q)
    {
        dim3 grid(64, NH);
        relpos_kernel<<<grid, 256>>>(rph, relh, 0);
        relpos_kernel<<<grid, 256>>>(rpw, relw, 1);
    }
    // 3. tf32 mma.sync flash attention with bias
    {
        dim3 grid(S_TOK / 128, NH);
        flash_mma_kernel<<<grid, 128, FLASH_SMEM>>>(attno);
    }
    // 4. out = attno @ proj_w + proj_b
    {
        dim3 grid(CDIM / 128, S_TOK / 128);
        gemm_bias_kernel<<<grid, 256>>>(attno, proj_w, proj_b, out,
                                        S_TOK, CDIM, CDIM);
    }
}

// round 6
// speedup vs baseline: 2.0506x; 1.3190x over previous
#include <cuda_runtime.h>
#include <cuda_bf16.h>
#include <cstdint>
#include <cstddef>

// Problem constants
#define S_TOK 4096      // H*W
#define CDIM  768
#define NH    12
#define QKV_N (3*CDIM)  // 2304

// ---------------------------------------------------------------------------
// Scratch (device globals; no dynamic allocation allowed)
// ---------------------------------------------------------------------------
__device__ float g_qkv[(size_t)S_TOK * QKV_N];        // [token][3*768]
__device__ float g_relh[(size_t)NH * S_TOK * 64];     // [h][q][kh]
__device__ float g_relw[(size_t)NH * S_TOK * 64];     // [h][q][kw]
__device__ float g_attno[(size_t)S_TOK * CDIM];       // [token][h*64+d]

// ---------------------------------------------------------------------------
// tf32 mma.sync helpers (sm_80-level PTX; works on compute_103 base target)
// ---------------------------------------------------------------------------
__device__ __forceinline__ uint32_t f2tf32(float f) {
    uint32_t u;
    asm("cvt.rna.tf32.f32 %0, %1;" : "=r"(u) : "f"(f));
    return u;
}

__device__ __forceinline__ void mma_tf32(float* c, const uint4& a, const uint2& b) {
    asm volatile(
        "mma.sync.aligned.m16n8k8.row.col.f32.tf32.tf32.f32 "
        "{%0,%1,%2,%3}, {%4,%5,%6,%7}, {%8,%9}, {%0,%1,%2,%3};"
        : "+f"(c[0]), "+f"(c[1]), "+f"(c[2]), "+f"(c[3])
        : "r"(a.x), "r"(a.y), "r"(a.z), "r"(a.w), "r"(b.x), "r"(b.y));
}

// ---------------------------------------------------------------------------
// tf32 tensor-core GEMM + bias: C[M,N] = A[M,K] @ B[K,N] + bias[N]
// 128x128 tile, BK=16, 256 threads (8 warps: 4 along M x 2 along N),
// double-buffered fragment-order SMEM. M%128==0, N%128==0, K%16==0.
// ---------------------------------------------------------------------------
__global__ __launch_bounds__(256, 2) void gemm_tf32_kernel(
    const float* __restrict__ A, const float* __restrict__ B,
    const float* __restrict__ bias, float* __restrict__ C,
    int M, int N, int K)
{
    __shared__ __align__(16) uint32_t sAf[2][2048];  // [ks2][wm4][mb2][lane32][4]
    __shared__ __align__(16) uint32_t sBf[2][2048];  // [ks2][wn2][nt8][lane32][2]

    const int tid  = threadIdx.x;
    const int lane = tid & 31;
    const int w    = tid >> 5;
    const int wm   = w & 3;
    const int wn   = w >> 2;
    const int m0   = blockIdx.y * 128;
    const int n0   = blockIdx.x * 128;

    float Ca[2][8][4];
#pragma unroll
    for (int mb = 0; mb < 2; mb++)
#pragma unroll
        for (int nt = 0; nt < 8; nt++)
#pragma unroll
            for (int j = 0; j < 4; j++) Ca[mb][nt][j] = 0.f;

    // loader addressing
    const int arow = tid >> 1;            // 0..127
    const int ac0  = (tid & 1) * 8;       // k-local base (0 or 8)
    const int brow = tid >> 4;            // 0..15 (k row)
    const int bc0  = (tid & 15) * 8;      // n-local base

    const int rr   = arow & 15;
    const int awm  = arow >> 5;
    const int amb  = (arow >> 4) & 1;
    const int aln  = (rr & 7) * 4;
    const int afi  = rr >> 3;
    const int aks  = ac0 >> 3;
    const int areg = ((aks * 4 + awm) * 2 + amb) * 32;

    const int bks  = brow >> 3;
    const int bkk  = brow & 7;
    const int bslot = bkk >> 2;
    const int bkl  = bkk & 3;
    const int bwn  = bc0 >> 6;
    const int bnt  = (bc0 >> 3) & 7;
    const int breg = ((bks * 2 + bwn) * 8 + bnt) * 32;

    const int nk = K / 16;

    float4 a0, a1, b0, b1;
    {
        const float* Ap = A + (size_t)(m0 + arow) * K + ac0;
        const float* Bp = B + (size_t)brow * N + n0 + bc0;
        a0 = *(const float4*)Ap;       a1 = *(const float4*)(Ap + 4);
        b0 = *(const float4*)Bp;       b1 = *(const float4*)(Bp + 4);
    }
    // stage chunk 0 into buf 0
    {
        float ae[8] = {a0.x,a0.y,a0.z,a0.w,a1.x,a1.y,a1.z,a1.w};
        float be[8] = {b0.x,b0.y,b0.z,b0.w,b1.x,b1.y,b1.z,b1.w};
#pragma unroll
        for (int i = 0; i < 8; i++) {
            sAf[0][(areg + aln + (i & 3)) * 4 + afi + 2 * (i >> 2)] = f2tf32(ae[i]);
            sBf[0][(breg + i * 4 + bkl) * 2 + bslot] = f2tf32(be[i]);
        }
    }
    __syncthreads();

    for (int kc = 0; kc < nk; kc++) {
        const int buf = kc & 1;
        if (kc + 1 < nk) {
            const int k0 = (kc + 1) * 16;
            const float* Ap = A + (size_t)(m0 + arow) * K + k0 + ac0;
            const float* Bp = B + (size_t)(k0 + brow) * N + n0 + bc0;
            a0 = *(const float4*)Ap;   a1 = *(const float4*)(Ap + 4);
            b0 = *(const float4*)Bp;   b1 = *(const float4*)(Bp + 4);
        }

#pragma unroll
        for (int ks = 0; ks < 2; ks++) {
            uint4 A0 = *(uint4*)&sAf[buf][(((ks * 4 + wm) * 2 + 0) * 32 + lane) * 4];
            uint4 A1 = *(uint4*)&sAf[buf][(((ks * 4 + wm) * 2 + 1) * 32 + lane) * 4];
#pragma unroll
            for (int nt = 0; nt < 8; nt++) {
                uint2 bb = *(uint2*)&sBf[buf][(((ks * 2 + wn) * 8 + nt) * 32 + lane) * 2];
                mma_tf32(Ca[0][nt], A0, bb);
                mma_tf32(Ca[1][nt], A1, bb);
            }
        }

        if (kc + 1 < nk) {
            const int nb = buf ^ 1;
            float ae[8] = {a0.x,a0.y,a0.z,a0.w,a1.x,a1.y,a1.z,a1.w};
            float be[8] = {b0.x,b0.y,b0.z,b0.w,b1.x,b1.y,b1.z,b1.w};
#pragma unroll
            for (int i = 0; i < 8; i++) {
                sAf[nb][(areg + aln + (i & 3)) * 4 + afi + 2 * (i >> 2)] = f2tf32(ae[i]);
                sBf[nb][(breg + i * 4 + bkl) * 2 + bslot] = f2tf32(be[i]);
            }
            __syncthreads();
        }
    }

    // epilogue
#pragma unroll
    for (int mb = 0; mb < 2; mb++) {
        int row = m0 + wm * 32 + mb * 16 + (lane >> 2);
#pragma unroll
        for (int nt = 0; nt < 8; nt++) {
            int col = n0 + wn * 64 + nt * 8 + 2 * (lane & 3);
            float bx = bias[col], by = bias[col + 1];
            float2 v0 = {Ca[mb][nt][0] + bx, Ca[mb][nt][1] + by};
            float2 v1 = {Ca[mb][nt][2] + bx, Ca[mb][nt][3] + by};
            *(float2*)(C + (size_t)row * N + col)       = v0;
            *(float2*)(C + (size_t)(row + 8) * N + col) = v1;
        }
    }
}

// ---------------------------------------------------------------------------
// Relative-position tables (unchanged, exact fp32)
// ---------------------------------------------------------------------------
__global__ __launch_bounds__(256) void relpos_kernel(
    const float* __restrict__ relpos, float* __restrict__ tbl, int mode)
{
    __shared__ __align__(16) float Qt[64][68];
    __shared__ __align__(16) float Rt[64][68];

    const int tid = threadIdx.x;
    const int h = blockIdx.y;
    const int fixed = blockIdx.x;

#pragma unroll
    for (int p = 0; p < 4; p++) {
        int f4 = tid + 256 * p;
        int r = f4 >> 4;
        int c4 = (f4 & 15) << 2;
        int token = (mode == 0) ? (fixed * 64 + r) : (r * 64 + fixed);
        *(float4*)&Qt[r][c4] =
            *(const float4*)(g_qkv + (size_t)token * QKV_N + h * 64 + c4);
        int ridx = fixed - r + 63;
        *(float4*)&Rt[r][c4] = *(const float4*)(relpos + ridx * 64 + c4);
    }
    __syncthreads();

    const int tx = tid & 15;
    const int ty = tid >> 4;
    float s[4][4];
#pragma unroll
    for (int i = 0; i < 4; i++)
#pragma unroll
        for (int j = 0; j < 4; j++) s[i][j] = 0.f;

#pragma unroll
    for (int c4 = 0; c4 < 16; c4++) {
        float qr[4][4], kr[4][4];
#pragma unroll
        for (int i = 0; i < 4; i++)
            *(float4*)&qr[i][0] = *(float4*)&Qt[ty + 16 * i][c4 * 4];
#pragma unroll
        for (int j = 0; j < 4; j++)
            *(float4*)&kr[j][0] = *(float4*)&Rt[tx + 16 * j][c4 * 4];
#pragma unroll
        for (int e = 0; e < 4; e++)
#pragma unroll
            for (int i = 0; i < 4; i++)
#pragma unroll
                for (int j = 0; j < 4; j++)
                    s[i][j] += qr[i][e] * kr[j][e];
    }

#pragma unroll
    for (int i = 0; i < 4; i++) {
        int a = ty + 16 * i;
        int token = (mode == 0) ? (fixed * 64 + a) : (a * 64 + fixed);
#pragma unroll
        for (int j = 0; j < 4; j++) {
            int b = tx + 16 * j;
            tbl[((size_t)h * S_TOK + token) * 64 + b] = s[i][j];
        }
    }
}

// ---------------------------------------------------------------------------
// Flash attention with tf32 mma.sync (m16n8k8), 256 threads / 8 warps.
// Warp w owns q rows [w*16, w*16+16). Key tiles of 64 keys (one kh row).
// Q A-frags + rel_w bias (C-frag order) live in REGISTERS (tile-invariant).
// SMEM: P stage (A-frag), rel_h rows, K/V B-frags (padded regions, 68 words).
//   sKf layout: [nt][ks] regions;  sVf layout: [ks][nt] regions.
// ---------------------------------------------------------------------------
#define PF_OFF   0            // 8192 u32 = 32KB
#define RHS_OFF  32768        // 128*68 f32 = 34816B
#define KF_OFF   67584        // 64 regions * 68 words * 4B = 17408B
#define VF_OFF   84992        // 17408B
#define FLASH_SMEM 102400

__global__ __launch_bounds__(256, 1) void flash_mma_kernel(float* __restrict__ out)
{
    extern __shared__ __align__(16) char smc[];
    uint32_t* sPf  = (uint32_t*)(smc + PF_OFF);
    float*    sRHs = (float*)   (smc + RHS_OFF);
    uint32_t* sKf  = (uint32_t*)(smc + KF_OFF);
    uint32_t* sVf  = (uint32_t*)(smc + VF_OFF);

    const int tid  = threadIdx.x;
    const int w    = tid >> 5;
    const int lane = tid & 31;
    const int h    = blockIdx.y;
    const int q0   = blockIdx.x * 128;

    // ---- prologue: rel_h rows -> smem ----
    {
        int r  = tid >> 1;
        int c0 = (tid & 1) * 32;
        const float* rhrow = g_relh + ((size_t)h * S_TOK + q0 + r) * 64 + c0;
#pragma unroll
        for (int c4 = 0; c4 < 32; c4 += 4)
            *(float4*)(sRHs + r * 68 + c0 + c4) = *(const float4*)(rhrow + c4);
    }

    // ---- prologue: Q A-frags + rel_w C-frags in registers ----
    const int rq = lane >> 2;                 // row-in-16 (low half)
    const int r0 = q0 + w * 16 + rq;          // global q row (low)
    uint4  Qa[8];
    float4 RWr[8];
    {
        const float* qp0 = g_qkv + (size_t)r0 * QKV_N + h * 64;
        const float* qp8 = qp0 + (size_t)8 * QKV_N;
        const int c0 = lane & 3;
#pragma unroll
        for (int ks = 0; ks < 8; ks++) {
            Qa[ks].x = f2tf32(qp0[ks * 8 + c0]     * 0.125f);
            Qa[ks].y = f2tf32(qp8[ks * 8 + c0]     * 0.125f);
            Qa[ks].z = f2tf32(qp0[ks * 8 + c0 + 4] * 0.125f);
            Qa[ks].w = f2tf32(qp8[ks * 8 + c0 + 4] * 0.125f);
        }
        const float* rw0 = g_relw + ((size_t)h * S_TOK + r0) * 64;
        const float* rw8 = rw0 + 8 * 64;
        const int nb = 2 * (lane & 3);
#pragma unroll
        for (int nt = 0; nt < 8; nt++) {
            RWr[nt].x = rw0[nt * 8 + nb];
            RWr[nt].y = rw0[nt * 8 + nb + 1];
            RWr[nt].z = rw8[nt * 8 + nb];
            RWr[nt].w = rw8[nt * 8 + nb + 1];
        }
    }
    __syncthreads();

    float Oa[8][4];
    float m_lo = -1e30f, m_hi = -1e30f, l_lo = 0.f, l_hi = 0.f;
#pragma unroll
    for (int nt = 0; nt < 8; nt++)
#pragma unroll
        for (int j = 0; j < 4; j++) Oa[nt][j] = 0.f;

    // P-scatter addressing (C-frag -> A-frag)
    const int g0 = 2 * (lane & 3);
    const int g1 = g0 + 1;
    const int lam0 = (rq << 2) + (g0 & 3);
    const int lam1 = (rq << 2) + (g1 & 3);
    const int fb0  = (g0 >> 2) << 1;
    const int fb1  = (g1 >> 2) << 1;

    // K/V loader addressing
    const int lr = tid >> 2;            // key row 0..63
    const int cb = (tid & 3) * 16;      // col base
    const int ntK = lr >> 3;
    const int l0K = (lr & 7) * 4;
    const int ksV = lr >> 3;
    const int slotV = (lr & 7) >> 2;
    const int rlV = lr & 3;

    for (int kt = 0; kt < 64; kt++) {
        // ---- gmem loads for K,V tile (to regs) ----
        const float* kb = g_qkv + (size_t)(kt * 64 + lr) * QKV_N + h * 64 + CDIM + cb;
        const float* vb = kb + CDIM;
        float4 ka[4], va[4];
#pragma unroll
        for (int t = 0; t < 4; t++) {
            ka[t] = *(const float4*)(kb + 4 * t);
            va[t] = *(const float4*)(vb + 4 * t);
        }
        __syncthreads();   // prior tile's sKf/sVf consumers done

        // ---- STS K (B-frag pairs, [nt][ks] regions) ----
#pragma unroll
        for (int g = 0; g < 2; g++) {
            int ks = (cb >> 3) + g;
            uint32_t* dst = sKf + (ntK * 8 + ks) * 68 + l0K * 2;
            float4 A4 = ka[2 * g], B4 = ka[2 * g + 1];
            uint4 s1 = {f2tf32(A4.x), f2tf32(B4.x), f2tf32(A4.y), f2tf32(B4.y)};
            uint4 s2 = {f2tf32(A4.z), f2tf32(B4.z), f2tf32(A4.w), f2tf32(B4.w)};
            *(uint4*)dst       = s1;
            *(uint4*)(dst + 4) = s2;
        }
        // ---- STS V ([ks][nt] regions, scatter) ----
#pragma unroll
        for (int g = 0; g < 2; g++) {
            int ntv = (cb >> 3) + g;
            uint32_t* vd = sVf + (ksV * 8 + ntv) * 68;
            float ve[8] = {va[2*g].x, va[2*g].y, va[2*g].z, va[2*g].w,
                           va[2*g+1].x, va[2*g+1].y, va[2*g+1].z, va[2*g+1].w};
#pragma unroll
            for (int e = 0; e < 8; e++)
                vd[(e * 4 + rlV) * 2 + slotV] = f2tf32(ve[e]);
        }
        __syncthreads();

        // ---- S = Q @ K^T ----
        float Sa[8][4];
#pragma unroll
        for (int nt = 0; nt < 8; nt++)
#pragma unroll
            for (int j = 0; j < 4; j++) Sa[nt][j] = 0.f;

#pragma unroll
        for (int ks = 0; ks < 8; ks++) {
#pragma unroll
            for (int nt = 0; nt < 8; nt++) {
                uint2 b = *(uint2*)(sKf + (nt * 8 + ks) * 68 + lane * 2);
                mma_tf32(Sa[nt], Qa[ks], b);
            }
        }

        // ---- bias + online softmax ----
        float rhl = sRHs[(w * 16 + rq) * 68 + kt];
        float rhh = sRHs[(w * 16 + rq + 8) * 68 + kt];
        float mlo = -1e30f, mhi = -1e30f;
#pragma unroll
        for (int nt = 0; nt < 8; nt++) {
            Sa[nt][0] += rhl + RWr[nt].x;
            Sa[nt][1] += rhl + RWr[nt].y;
            Sa[nt][2] += rhh + RWr[nt].z;
            Sa[nt][3] += rhh + RWr[nt].w;
            mlo = fmaxf(mlo, fmaxf(Sa[nt][0], Sa[nt][1]));
            mhi = fmaxf(mhi, fmaxf(Sa[nt][2], Sa[nt][3]));
        }
        mlo = fmaxf(mlo, __shfl_xor_sync(0xffffffffu, mlo, 1));
        mlo = fmaxf(mlo, __shfl_xor_sync(0xffffffffu, mlo, 2));
        mhi = fmaxf(mhi, __shfl_xor_sync(0xffffffffu, mhi, 1));
        mhi = fmaxf(mhi, __shfl_xor_sync(0xffffffffu, mhi, 2));
        float mnl = fmaxf(m_lo, mlo);
        float mnh = fmaxf(m_hi, mhi);
        float al  = __expf(m_lo - mnl);
        float ah  = __expf(m_hi - mnh);
        m_lo = mnl; m_hi = mnh;

        float rsl = 0.f, rsh = 0.f;
#pragma unroll
        for (int nt = 0; nt < 8; nt++) {
            float p0 = __expf(Sa[nt][0] - mnl);
            float p1 = __expf(Sa[nt][1] - mnl);
            float p2 = __expf(Sa[nt][2] - mnh);
            float p3 = __expf(Sa[nt][3] - mnh);
            rsl += p0 + p1;
            rsh += p2 + p3;
            uint32_t base = (w * 8 + nt) * 32;
            uint2 u0 = {f2tf32(p0), f2tf32(p2)};
            uint2 u1 = {f2tf32(p1), f2tf32(p3)};
            *(uint2*)(sPf + (base + lam0) * 4 + fb0) = u0;
            *(uint2*)(sPf + (base + lam1) * 4 + fb1) = u1;
        }
        rsl += __shfl_xor_sync(0xffffffffu, rsl, 1);
        rsl += __shfl_xor_sync(0xffffffffu, rsl, 2);
        rsh += __shfl_xor_sync(0xffffffffu, rsh, 1);
        rsh += __shfl_xor_sync(0xffffffffu, rsh, 2);
        l_lo = l_lo * al + rsl;
        l_hi = l_hi * ah + rsh;

        // ---- pre-scale O, then O += P @ V ----
#pragma unroll
        for (int nt = 0; nt < 8; nt++) {
            Oa[nt][0] *= al;
            Oa[nt][1] *= al;
            Oa[nt][2] *= ah;
            Oa[nt][3] *= ah;
        }
        __syncwarp();

#pragma unroll
        for (int ks = 0; ks < 8; ks++) {
            uint4 p = *(uint4*)(sPf + ((w * 8 + ks) * 32 + lane) * 4);
#pragma unroll
            for (int nt = 0; nt < 8; nt++) {
                uint2 b = *(uint2*)(sVf + (ks * 8 + nt) * 68 + lane * 2);
                mma_tf32(Oa[nt], p, b);
            }
        }
    }

    // ---- epilogue: normalize, store ----
    float invl = 1.f / l_lo;
    float invh = 1.f / l_hi;
#pragma unroll
    for (int nt = 0; nt < 8; nt++) {
        int col = h * 64 + nt * 8 + 2 * (lane & 3);
        float2 v0 = {Oa[nt][0] * invl, Oa[nt][1] * invl};
        float2 v1 = {Oa[nt][2] * invh, Oa[nt][3] * invh};
        *(float2*)(out + (size_t)r0 * CDIM + col)       = v0;
        *(float2*)(out + (size_t)(r0 + 8) * CDIM + col) = v1;
    }
}

// ---------------------------------------------------------------------------
// Launch
// ---------------------------------------------------------------------------
extern "C" void kernel_launch(void* const* d_in, const int* in_sizes, int n_in,
                              void* d_out, int out_size)
{
    const float* x      = (const float*)d_in[0];
    const float* qkv_w  = (const float*)d_in[1];
    const float* qkv_b  = (const float*)d_in[2];
    const float* rph    = (const float*)d_in[3];
    const float* rpw    = (const float*)d_in[4];
    const float* proj_w = (const float*)d_in[5];
    const float* proj_b = (const float*)d_in[6];
    float* out = (float*)d_out;

    float *qkv, *relh, *relw, *attno;
    cudaGetSymbolAddress((void**)&qkv,   g_qkv);
    cudaGetSymbolAddress((void**)&relh,  g_relh);
    cudaGetSymbolAddress((void**)&relw,  g_relw);
    cudaGetSymbolAddress((void**)&attno, g_attno);

    cudaFuncSetAttribute(flash_mma_kernel,
                         cudaFuncAttributeMaxDynamicSharedMemorySize,
                         FLASH_SMEM);

    // 1. qkv = x @ qkv_w + qkv_b  (tf32 tensor GEMM)
    {
        dim3 grid(QKV_N / 128, S_TOK / 128);
        gemm_tf32_kernel<<<grid, 256>>>(x, qkv_w, qkv_b, qkv,
                                        S_TOK, QKV_N, CDIM);
    }
    // 2. rel-pos tables (from unscaled q)
    {
        dim3 grid(64, NH);
        relpos_kernel<<<grid, 256>>>(rph, relh, 0);
        relpos_kernel<<<grid, 256>>>(rpw, relw, 1);
    }
    // 3. tf32 mma.sync flash attention with bias
    {
        dim3 grid(S_TOK / 128, NH);
        flash_mma_kernel<<<grid, 256, FLASH_SMEM>>>(attno);
    }
    // 4. out = attno @ proj_w + proj_b  (tf32 tensor GEMM)
    {
        dim3 grid(CDIM / 128, S_TOK / 128);
        gemm_tf32_kernel<<<grid, 256>>>(attno, proj_w, proj_b, out,
                                        S_TOK, CDIM, CDIM);
    }
}

// round 8
// speedup vs baseline: 2.7105x; 1.3218x over previous
#include <cuda_runtime.h>
#include <cuda_bf16.h>
#include <cstdint>
#include <cstddef>

// Problem constants
#define S_TOK 4096      // H*W
#define CDIM  768
#define NH    12
#define QKV_N (3*CDIM)  // 2304

// ---------------------------------------------------------------------------
// Scratch (device globals; no dynamic allocation allowed)
// ---------------------------------------------------------------------------
__device__ float g_qkv[(size_t)S_TOK * QKV_N];        // [token][3*768]
__device__ float g_relh[(size_t)NH * 64 * S_TOK];     // [h][kh][q]  (transposed!)
__device__ float g_relw[(size_t)NH * S_TOK * 64];     // [h][q][kw]
__device__ float g_attno[(size_t)S_TOK * CDIM];       // [token][h*64+d]
__device__ float g_xr[(size_t)S_TOK * CDIM];          // tf32-rounded x
__device__ float g_wr[(size_t)CDIM * QKV_N];          // tf32-rounded weights

// ---------------------------------------------------------------------------
// Helpers
// ---------------------------------------------------------------------------
__device__ __forceinline__ uint32_t f2tf32(float f) {
    uint32_t u;
    asm("cvt.rna.tf32.f32 %0, %1;" : "=r"(u) : "f"(f));
    return u;
}

__device__ __forceinline__ void mma_tf32(float* c, const uint4& a, const uint2& b) {
    asm volatile(
        "mma.sync.aligned.m16n8k8.row.col.f32.tf32.tf32.f32 "
        "{%0,%1,%2,%3}, {%4,%5,%6,%7}, {%8,%9}, {%0,%1,%2,%3};"
        : "+f"(c[0]), "+f"(c[1]), "+f"(c[2]), "+f"(c[3])
        : "r"(a.x), "r"(a.y), "r"(a.z), "r"(a.w), "r"(b.x), "r"(b.y));
}

__device__ __forceinline__ uint32_t smem_u32(const void* p) {
    uint32_t a;
    asm("{ .reg .u64 t; cvta.to.shared.u64 t, %1; cvt.u32.u64 %0, t; }"
        : "=r"(a) : "l"(p));
    return a;
}

__device__ __forceinline__ void cp16(uint32_t d, const void* s) {
    asm volatile("cp.async.cg.shared.global [%0], [%1], 16;" :: "r"(d), "l"(s));
}
#define CP_COMMIT() asm volatile("cp.async.commit_group;" ::: "memory")
#define CP_WAIT1()  asm volatile("cp.async.wait_group 1;" ::: "memory")
#define CP_WAIT0()  asm volatile("cp.async.wait_group 0;" ::: "memory")

// ---------------------------------------------------------------------------
// tf32 rounding pass (rna) — makes MMA truncation exact
// ---------------------------------------------------------------------------
__global__ __launch_bounds__(256) void tf32_round_kernel(
    const float* __restrict__ in, float* __restrict__ out, int n4)
{
    int i = blockIdx.x * blockDim.x + threadIdx.x;
    if (i >= n4) return;
    float4 v = ((const float4*)in)[i];
    uint4 u;
    u.x = f2tf32(v.x); u.y = f2tf32(v.y); u.z = f2tf32(v.z); u.w = f2tf32(v.w);
    ((uint4*)out)[i] = u;
}

// ---------------------------------------------------------------------------
// tf32 tensor GEMM + bias, cp.async double-buffered raw tiles.
// Inputs A,B must be pre-rounded to tf32 (raw-bit operands).
// 128x128 tile, BK=16, 256 threads (8 warps: 4 M x 2 N).
// A tile smem [128][20] (bank-safe), B tile [16][136].
// ---------------------------------------------------------------------------
__global__ __launch_bounds__(256, 2) void gemm_tf32_kernel(
    const float* __restrict__ A, const float* __restrict__ B,
    const float* __restrict__ bias, float* __restrict__ C,
    int M, int N, int K)
{
    __shared__ __align__(16) float sA[2][128 * 20];
    __shared__ __align__(16) float sB[2][16 * 136];

    const int tid  = threadIdx.x;
    const int lane = tid & 31;
    const int w    = tid >> 5;
    const int wm   = w & 3;
    const int wn   = w >> 2;
    const int m0   = blockIdx.y * 128;
    const int n0   = blockIdx.x * 128;
    const int nk   = K / 16;

    float Ca[2][8][4];
#pragma unroll
    for (int mb = 0; mb < 2; mb++)
#pragma unroll
        for (int nt = 0; nt < 8; nt++)
#pragma unroll
            for (int j = 0; j < 4; j++) Ca[mb][nt][j] = 0.f;

    // loader chunk mapping: 2 A-chunks + 2 B-chunks per thread
    const int ac  = tid * 2;
    const int ar0 = ac >> 2, aci0 = (ac & 3) * 4;
    const int ar1 = (ac + 1) >> 2, aci1 = ((ac + 1) & 3) * 4;
    const int bc  = tid * 2;
    const int br0 = bc >> 5, bci0 = (bc & 31) * 4;
    const int br1 = (bc + 1) >> 5, bci1 = ((bc + 1) & 31) * 4;

    auto issue = [&](int kc, int buf) {
        uint32_t ab = smem_u32(&sA[buf][0]);
        uint32_t bb = smem_u32(&sB[buf][0]);
        int k0 = kc * 16;
        cp16(ab + (ar0 * 20 + aci0) * 4, A + (size_t)(m0 + ar0) * K + k0 + aci0);
        cp16(ab + (ar1 * 20 + aci1) * 4, A + (size_t)(m0 + ar1) * K + k0 + aci1);
        cp16(bb + (br0 * 136 + bci0) * 4, B + (size_t)(k0 + br0) * N + n0 + bci0);
        cp16(bb + (br1 * 136 + bci1) * 4, B + (size_t)(k0 + br1) * N + n0 + bci1);
        CP_COMMIT();
    };

    issue(0, 0);

    for (int kc = 0; kc < nk; kc++) {
        const int buf = kc & 1;
        __syncthreads();                       // prev compute done (buffers free)
        if (kc + 1 < nk) { issue(kc + 1, buf ^ 1); CP_WAIT1(); }
        else             { CP_WAIT0(); }
        __syncthreads();                       // tile kc visible

        const uint32_t* ap = (const uint32_t*)&sA[buf][0]
                           + (wm * 32 + (lane >> 2)) * 20 + (lane & 3);
        const uint32_t* bp = (const uint32_t*)&sB[buf][0]
                           + (lane & 3) * 136 + wn * 64 + (lane >> 2);
#pragma unroll
        for (int ks = 0; ks < 2; ks++) {
            const uint32_t* a = ap + ks * 8;
            uint4 A0 = {a[0],        a[8 * 20],        a[4],        a[8 * 20 + 4]};
            uint4 A1 = {a[16 * 20],  a[24 * 20],       a[16 * 20 + 4], a[24 * 20 + 4]};
            const uint32_t* b = bp + ks * 8 * 136;
#pragma unroll
            for (int nt = 0; nt < 8; nt++) {
                uint2 bb = {b[nt * 8], b[4 * 136 + nt * 8]};
                mma_tf32(Ca[0][nt], A0, bb);
                mma_tf32(Ca[1][nt], A1, bb);
            }
        }
    }

    // epilogue
#pragma unroll
    for (int mb = 0; mb < 2; mb++) {
        int row = m0 + wm * 32 + mb * 16 + (lane >> 2);
#pragma unroll
        for (int nt = 0; nt < 8; nt++) {
            int col = n0 + wn * 64 + nt * 8 + 2 * (lane & 3);
            float bx = bias[col], by = bias[col + 1];
            float2 v0 = {Ca[mb][nt][0] + bx, Ca[mb][nt][1] + by};
            float2 v1 = {Ca[mb][nt][2] + bx, Ca[mb][nt][3] + by};
            *(float2*)(C + (size_t)row * N + col)       = v0;
            *(float2*)(C + (size_t)(row + 8) * N + col) = v1;
        }
    }
}

// ---------------------------------------------------------------------------
// Relative-position tables (exact fp32).
// mode 0 (rel_h): store TRANSPOSED  tbl[h][kh][q]  for coalesced flash loads.
// mode 1 (rel_w): store             tbl[h][q][kw].
// ---------------------------------------------------------------------------
__global__ __launch_bounds__(256) void relpos_kernel(
    const float* __restrict__ relpos, float* __restrict__ tbl, int mode)
{
    __shared__ __align__(16) float Qt[64][68];
    __shared__ __align__(16) float Rt[64][68];

    const int tid = threadIdx.x;
    const int h = blockIdx.y;
    const int fixed = blockIdx.x;

#pragma unroll
    for (int p = 0; p < 4; p++) {
        int f4 = tid + 256 * p;
        int r = f4 >> 4;
        int c4 = (f4 & 15) << 2;
        int token = (mode == 0) ? (fixed * 64 + r) : (r * 64 + fixed);
        *(float4*)&Qt[r][c4] =
            *(const float4*)(g_qkv + (size_t)token * QKV_N + h * 64 + c4);
        int ridx = fixed - r + 63;
        *(float4*)&Rt[r][c4] = *(const float4*)(relpos + ridx * 64 + c4);
    }
    __syncthreads();

    const int tx = tid & 15;
    const int ty = tid >> 4;
    float s[4][4];
#pragma unroll
    for (int i = 0; i < 4; i++)
#pragma unroll
        for (int j = 0; j < 4; j++) s[i][j] = 0.f;

#pragma unroll
    for (int c4 = 0; c4 < 16; c4++) {
        float qr[4][4], kr[4][4];
#pragma unroll
        for (int i = 0; i < 4; i++)
            *(float4*)&qr[i][0] = *(float4*)&Qt[ty + 16 * i][c4 * 4];
#pragma unroll
        for (int j = 0; j < 4; j++)
            *(float4*)&kr[j][0] = *(float4*)&Rt[tx + 16 * j][c4 * 4];
#pragma unroll
        for (int e = 0; e < 4; e++)
#pragma unroll
            for (int i = 0; i < 4; i++)
#pragma unroll
                for (int j = 0; j < 4; j++)
                    s[i][j] += qr[i][e] * kr[j][e];
    }

#pragma unroll
    for (int i = 0; i < 4; i++) {
        int a = ty + 16 * i;
        int token = (mode == 0) ? (fixed * 64 + a) : (a * 64 + fixed);
#pragma unroll
        for (int j = 0; j < 4; j++) {
            int b = tx + 16 * j;
            if (mode == 0)
                tbl[((size_t)h * 64 + b) * S_TOK + token] = s[i][j];
            else
                tbl[((size_t)h * S_TOK + token) * 64 + b] = s[i][j];
        }
    }
}

// ---------------------------------------------------------------------------
// Flash attention, tf32 mma.sync, cp.async double-buffered raw K/V.
// 256 threads / 8 warps, warp owns 16 q rows; q-tile 128; key tiles of 64.
// g_qkv must be pre-rounded to tf32. K tile smem [64][68], V tile [64][72]
// (dual padding -> conflict-free raw B-frag LDS.32 pairs).
// SMEM map:
//   RWF  [8w][8nt][32][4] f32  (same-thread rel_w C-frag slots)  32768 B
//   PF   [8w][2 regions][32][4] u32 (P quarter-pass staging)      8192 B
//   K0 17408 | V0 18432 | K1 17408 | V1 18432                    71680 B
// ---------------------------------------------------------------------------
#define RWF_OFF  0
#define PF_OFF   32768
#define KV_OFF   40960
#define KVSTRIDE 35840
#define FLASH_SMEM 112640

__global__ __launch_bounds__(256, 2) void flash_mma_kernel(float* __restrict__ out)
{
    extern __shared__ __align__(16) char smc[];
    float*    sRWf = (float*)(smc + RWF_OFF);
    uint32_t* sPf  = (uint32_t*)(smc + PF_OFF);
    const uint32_t smem_base = smem_u32(smc);

    const int tid  = threadIdx.x;
    const int w    = tid >> 5;
    const int lane = tid & 31;
    const int h    = blockIdx.y;
    const int q0   = blockIdx.x * 128;

    // ---- prologue: Q A-frags (raw tf32 bits; 0.125 scale is exact) ----
    const int rq = lane >> 2;
    const int r0 = q0 + w * 16 + rq;
    const int c0 = lane & 3;
    uint4 Qa[8];
    {
        const float* qp0 = g_qkv + (size_t)r0 * QKV_N + h * 64;
        const float* qp8 = qp0 + (size_t)8 * QKV_N;
#pragma unroll
        for (int ks = 0; ks < 8; ks++) {
            Qa[ks].x = __float_as_uint(qp0[ks * 8 + c0]     * 0.125f);
            Qa[ks].y = __float_as_uint(qp8[ks * 8 + c0]     * 0.125f);
            Qa[ks].z = __float_as_uint(qp0[ks * 8 + c0 + 4] * 0.125f);
            Qa[ks].w = __float_as_uint(qp8[ks * 8 + c0 + 4] * 0.125f);
        }
        // rel_w C-frag values -> same-thread smem slots
        const float* rw0 = g_relw + ((size_t)h * S_TOK + r0) * 64;
        const float* rw8 = rw0 + 8 * 64;
        const int nb = 2 * (lane & 3);
#pragma unroll
        for (int nt = 0; nt < 8; nt++) {
            float4 v = {rw0[nt * 8 + nb], rw0[nt * 8 + nb + 1],
                        rw8[nt * 8 + nb], rw8[nt * 8 + nb + 1]};
            *(float4*)(sRWf + ((w * 8 + nt) * 32 + lane) * 4) = v;
        }
    }

    float Oa[8][4];
    float m_lo = -1e30f, m_hi = -1e30f, l_lo = 0.f, l_hi = 0.f;
#pragma unroll
    for (int nt = 0; nt < 8; nt++)
#pragma unroll
        for (int j = 0; j < 4; j++) Oa[nt][j] = 0.f;

    // P-scatter addressing (C-frag -> A-frag)
    const int g0 = 2 * (lane & 3);
    const int g1 = g0 + 1;
    const int lam0 = (rq << 2) + (g0 & 3);
    const int lam1 = (rq << 2) + (g1 & 3);
    const int fb0  = (g0 >> 2) << 1;
    const int fb1  = (g1 >> 2) << 1;

    // cp.async loader mapping
    const int crow = tid >> 2;          // key row 0..63
    const int cq16 = (tid & 3) * 16;    // float offset of 4-chunk group

    auto issue_kv = [&](int t, int b) {
        const float* kp = g_qkv + (size_t)(t * 64 + crow) * QKV_N + h * 64 + CDIM + cq16;
        uint32_t kd = smem_base + KV_OFF + b * KVSTRIDE + (crow * 68 + cq16) * 4;
        uint32_t vd = smem_base + KV_OFF + b * KVSTRIDE + 17408 + (crow * 72 + cq16) * 4;
#pragma unroll
        for (int i = 0; i < 4; i++) {
            cp16(kd + i * 16, kp + i * 4);
            cp16(vd + i * 16, kp + CDIM + i * 4);
        }
        CP_COMMIT();
    };

    issue_kv(0, 0);

    const float* rh_base = g_relh + (size_t)h * 64 * S_TOK + q0 + w * 16 + rq;

    for (int kt = 0; kt < 64; kt++) {
        const int buf = kt & 1;
        __syncthreads();                        // prev tile's consumers done
        if (kt + 1 < 64) issue_kv(kt + 1, buf ^ 1);
        float rhl = __ldg(rh_base + (size_t)kt * S_TOK);
        float rhh = __ldg(rh_base + (size_t)kt * S_TOK + 8);
        if (kt + 1 < 64) { CP_WAIT1(); } else { CP_WAIT0(); }
        __syncthreads();                        // tile kt visible

        const uint32_t* kp = (const uint32_t*)(smc + KV_OFF + buf * KVSTRIDE)
                           + (lane >> 2) * 68 + (lane & 3);
        const uint32_t* vp = (const uint32_t*)(smc + KV_OFF + buf * KVSTRIDE + 17408)
                           + (lane & 3) * 72 + (lane >> 2);

        // ---- S = Q @ K^T ----
        float Sa[8][4];
#pragma unroll
        for (int nt = 0; nt < 8; nt++)
#pragma unroll
            for (int j = 0; j < 4; j++) Sa[nt][j] = 0.f;

#pragma unroll
        for (int ks = 0; ks < 8; ks++) {
#pragma unroll
            for (int nt = 0; nt < 8; nt++) {
                uint2 b = {kp[nt * 8 * 68 + ks * 8], kp[nt * 8 * 68 + ks * 8 + 4]};
                mma_tf32(Sa[nt], Qa[ks], b);
            }
        }

        // ---- bias + online softmax (P left in Sa) ----
        float mlo = -1e30f, mhi = -1e30f;
#pragma unroll
        for (int nt = 0; nt < 8; nt++) {
            float4 rw = *(float4*)(sRWf + ((w * 8 + nt) * 32 + lane) * 4);
            Sa[nt][0] += rhl + rw.x;
            Sa[nt][1] += rhl + rw.y;
            Sa[nt][2] += rhh + rw.z;
            Sa[nt][3] += rhh + rw.w;
            mlo = fmaxf(mlo, fmaxf(Sa[nt][0], Sa[nt][1]));
            mhi = fmaxf(mhi, fmaxf(Sa[nt][2], Sa[nt][3]));
        }
        mlo = fmaxf(mlo, __shfl_xor_sync(0xffffffffu, mlo, 1));
        mlo = fmaxf(mlo, __shfl_xor_sync(0xffffffffu, mlo, 2));
        mhi = fmaxf(mhi, __shfl_xor_sync(0xffffffffu, mhi, 1));
        mhi = fmaxf(mhi, __shfl_xor_sync(0xffffffffu, mhi, 2));
        float mnl = fmaxf(m_lo, mlo);
        float mnh = fmaxf(m_hi, mhi);
        float al  = __expf(m_lo - mnl);
        float ah  = __expf(m_hi - mnh);
        m_lo = mnl; m_hi = mnh;

        float rsl = 0.f, rsh = 0.f;
#pragma unroll
        for (int nt = 0; nt < 8; nt++) {
            float p0 = __expf(Sa[nt][0] - mnl);
            float p1 = __expf(Sa[nt][1] - mnl);
            float p2 = __expf(Sa[nt][2] - mnh);
            float p3 = __expf(Sa[nt][3] - mnh);
            rsl += p0 + p1;
            rsh += p2 + p3;
            Sa[nt][0] = p0; Sa[nt][1] = p1; Sa[nt][2] = p2; Sa[nt][3] = p3;
        }
        rsl += __shfl_xor_sync(0xffffffffu, rsl, 1);
        rsl += __shfl_xor_sync(0xffffffffu, rsl, 2);
        rsh += __shfl_xor_sync(0xffffffffu, rsh, 1);
        rsh += __shfl_xor_sync(0xffffffffu, rsh, 2);
        l_lo = l_lo * al + rsl;
        l_hi = l_hi * ah + rsh;

#pragma unroll
        for (int nt = 0; nt < 8; nt++) {
            Oa[nt][0] *= al;
            Oa[nt][1] *= al;
            Oa[nt][2] *= ah;
            Oa[nt][3] *= ah;
        }

        // ---- O += P @ V, quarter passes through 2-region P buffer ----
#pragma unroll
        for (int p = 0; p < 4; p++) {
#pragma unroll
            for (int e = 0; e < 2; e++) {
                int nt = 2 * p + e;
                int base = (w * 2 + (nt & 1)) * 32;
                uint2 u0 = {f2tf32(Sa[nt][0]), f2tf32(Sa[nt][2])};
                uint2 u1 = {f2tf32(Sa[nt][1]), f2tf32(Sa[nt][3])};
                *(uint2*)(sPf + (base + lam0) * 4 + fb0) = u0;
                *(uint2*)(sPf + (base + lam1) * 4 + fb1) = u1;
            }
            __syncwarp();
#pragma unroll
            for (int e = 0; e < 2; e++) {
                int ks = 2 * p + e;
                uint4 Pf = *(uint4*)(sPf + ((w * 2 + (ks & 1)) * 32 + lane) * 4);
#pragma unroll
                for (int nt = 0; nt < 8; nt++) {
                    uint2 b = {vp[ks * 8 * 72 + nt * 8],
                               vp[(ks * 8 + 4) * 72 + nt * 8]};
                    mma_tf32(Oa[nt], Pf, b);
                }
            }
            __syncwarp();
        }
    }

    // ---- epilogue: normalize, store ----
    float invl = 1.f / l_lo;
    float invh = 1.f / l_hi;
#pragma unroll
    for (int nt = 0; nt < 8; nt++) {
        int col = h * 64 + nt * 8 + 2 * (lane & 3);
        float2 v0 = {Oa[nt][0] * invl, Oa[nt][1] * invl};
        float2 v1 = {Oa[nt][2] * invh, Oa[nt][3] * invh};
        *(float2*)(out + (size_t)r0 * CDIM + col)       = v0;
        *(float2*)(out + (size_t)(r0 + 8) * CDIM + col) = v1;
    }
}

// ---------------------------------------------------------------------------
// Launch
// ---------------------------------------------------------------------------
extern "C" void kernel_launch(void* const* d_in, const int* in_sizes, int n_in,
                              void* d_out, int out_size)
{
    const float* x      = (const float*)d_in[0];
    const float* qkv_w  = (const float*)d_in[1];
    const float* qkv_b  = (const float*)d_in[2];
    const float* rph    = (const float*)d_in[3];
    const float* rpw    = (const float*)d_in[4];
    const float* proj_w = (const float*)d_in[5];
    const float* proj_b = (const float*)d_in[6];
    float* out = (float*)d_out;

    float *qkv, *relh, *relw, *attno, *xr, *wr;
    cudaGetSymbolAddress((void**)&qkv,   g_qkv);
    cudaGetSymbolAddress((void**)&relh,  g_relh);
    cudaGetSymbolAddress((void**)&relw,  g_relw);
    cudaGetSymbolAddress((void**)&attno, g_attno);
    cudaGetSymbolAddress((void**)&xr,    g_xr);
    cudaGetSymbolAddress((void**)&wr,    g_wr);

    cudaFuncSetAttribute(flash_mma_kernel,
                         cudaFuncAttributeMaxDynamicSharedMemorySize,
                         FLASH_SMEM);

    const int RB = 256;
    // 0. pre-round inputs to tf32 (makes MMA truncation exact rna rounding)
    {
        int n4 = (S_TOK * CDIM) / 4;
        tf32_round_kernel<<<(n4 + RB - 1) / RB, RB>>>(x, xr, n4);
        n4 = (CDIM * QKV_N) / 4;
        tf32_round_kernel<<<(n4 + RB - 1) / RB, RB>>>(qkv_w, wr, n4);
    }
    // 1. qkv = xr @ wr + qkv_b
    {
        dim3 grid(QKV_N / 128, S_TOK / 128);
        gemm_tf32_kernel<<<grid, 256>>>(xr, wr, qkv_b, qkv,
                                        S_TOK, QKV_N, CDIM);
    }
    // 1b. round qkv in place (Q/K/V all consumed as tf32 downstream)
    {
        int n4 = (S_TOK * QKV_N) / 4;
        tf32_round_kernel<<<(n4 + RB - 1) / RB, RB>>>(qkv, qkv, n4);
    }
    // 2. rel-pos tables (fp32 math on rounded q)
    {
        dim3 grid(64, NH);
        relpos_kernel<<<grid, 256>>>(rph, relh, 0);
        relpos_kernel<<<grid, 256>>>(rpw, relw, 1);
    }
    // 3. flash attention
    {
        dim3 grid(S_TOK / 128, NH);
        flash_mma_kernel<<<grid, 256, FLASH_SMEM>>>(attno);
    }
    // 4. round attention output + proj weights, then proj GEMM
    {
        int n4 = (S_TOK * CDIM) / 4;
        tf32_round_kernel<<<(n4 + RB - 1) / RB, RB>>>(attno, attno, n4);
        n4 = (CDIM * CDIM) / 4;
        tf32_round_kernel<<<(n4 + RB - 1) / RB, RB>>>(proj_w, wr, n4);
        dim3 grid(CDIM / 128, S_TOK / 128);
        gemm_tf32_kernel<<<grid, 256>>>(attno, wr, proj_b, out,
                                        S_TOK, CDIM, CDIM);
    }
}